// round 8
// baseline (speedup 1.0000x reference)
#include <cuda_runtime.h>

#define NB 8192
#define NT 1024
#define K  8                    // steps per tile
#define NTILES (NT / K)         // 128
#define RPB 64                  // robots per block (2 per thread)
#define OUTROW 6150             // (NT+1)*6 floats per robot
#define CMDROW (NT * 3)         // 3072 floats per robot
#define CPTF (K * 3)            // 24 cmd floats per robot-tile
#define SPTF (K * 6)            // 48 state floats per robot-tile
#define F2PT (SPTF / 2)         // 24 float2 per robot-tile
#define STRIDE_ST 50            // padded smem state row (floats, even for float2)

__device__ __forceinline__ float softplusf(float x) {
    return (x > 20.0f) ? x : log1pf(expf(x));
}
__device__ __forceinline__ float sgnf(float v) {
    return (v > 0.0f) ? 1.0f : ((v < 0.0f) ? -1.0f : 0.0f);
}

__global__ void __launch_bounds__(32)
omni_sim_kernel(const float* __restrict__ init,
                const float* __restrict__ cmd,
                const float* __restrict__ com,
                const float* __restrict__ pI,
                const float* __restrict__ pG,
                const float* __restrict__ pT,
                const float* __restrict__ pDv,
                const float* __restrict__ pDc,
                float* __restrict__ out)
{
    // commands, time-major transposed: [(3s+c)*64 + r], double-buffered (12 KB)
    __shared__ float s_cmd[2][CPTF * RPB];
    // state staging, robot-major: [r*50 + 6s + k] (12.8 KB)
    __shared__ float s_st[RPB * STRIDE_ST];

    const int lane = threadIdx.x;
    const int b0   = blockIdx.x * RPB;
    const int bA   = b0 + lane;
    const int bB   = b0 + lane + 32;

    const float DT      = 0.016f;
    const float PI_F    = 3.14159265358979323846f;
    const float TWOPI_F = 6.28318530717958647692f;

    const float inertia = softplusf(pI[0]) + 1e-4f;
    const float gain    = softplusf(pG[0]);
    const float grip    = softplusf(pT[0]);
    const float dv0 = softplusf(pDv[0]);
    const float dv1 = softplusf(pDv[1]);
    const float dv2 = softplusf(pDv[2]);
    const float dc0 = softplusf(pDc[0]);
    const float dc1 = softplusf(pDc[1]);
    const float dc2 = softplusf(pDc[2]);
    const float dxo = com[0];
    const float dyo = com[1];
    const float invM = 1.0f / 2.8f;
    const float invI = 1.0f / inertia;

    // A = gain * (M M^T) + grip * I   (M M^T off-diagonals G01=G02=0)
    const float A00 = gain * 2.6736481776669304f + grip;
    const float A11 = gain * 1.3263518223330696f + grip;
    const float A12 = gain * (-0.02570176974357713f);
    const float A22 = gain * 0.0324f + grip;

    // Load initial states + emit t=0 rows
    float xA, yA, thA, vxA, vyA, omA;
    float xB, yB, thB, vxB, vyB, omB;
    {
        const float2* iA = (const float2*)(init + (size_t)bA * 6);
        float2 a0 = iA[0], a1 = iA[1], a2 = iA[2];
        xA = a0.x; yA = a0.y; thA = a1.x; vxA = a1.y; vyA = a2.x; omA = a2.y;
        float2* oA = (float2*)(out + (size_t)bA * OUTROW);
        oA[0] = a0; oA[1] = a1; oA[2] = a2;
        const float2* iB = (const float2*)(init + (size_t)bB * 6);
        float2 c0 = iB[0], c1 = iB[1], c2 = iB[2];
        xB = c0.x; yB = c0.y; thB = c1.x; vxB = c1.y; vyB = c2.x; omB = c2.y;
        float2* oB = (float2*)(out + (size_t)bB * OUTROW);
        oB[0] = c0; oB[1] = c1; oB[2] = c2;
    }

    // Cooperative cmd-load mapping: 64 robots x 6 float4 = 384 float4 / 32 lanes
    const float* cmdbase = cmd + (size_t)b0 * CMDROW;
    int pf_goff[12];   // gmem float offset (within tile slice)
    int pf_soff[12];   // smem float offset of component j*4, robot r
#pragma unroll
    for (int i = 0; i < 12; i++) {
        int e = i * 32 + lane;
        int r = e / 6;
        int j = e - r * 6;
        pf_goff[i] = r * CMDROW + j * 4;
        pf_soff[i] = (j * 4) * RPB + r;     // +64 per component
    }

    // Preload tile 0 (transposed scatter)
#pragma unroll
    for (int i = 0; i < 12; i++) {
        float4 v = *(const float4*)(cmdbase + pf_goff[i]);
        s_cmd[0][pf_soff[i] + 0 * RPB] = v.x;
        s_cmd[0][pf_soff[i] + 1 * RPB] = v.y;
        s_cmd[0][pf_soff[i] + 2 * RPB] = v.z;
        s_cmd[0][pf_soff[i] + 3 * RPB] = v.w;
    }
    __syncwarp();

    float* mystA = &s_st[lane * STRIDE_ST];
    float* mystB = &s_st[(lane + 32) * STRIDE_ST];

    // Store-phase mapping: 64 robots x 24 float2 = 1536 / 32 lanes = 48 iters
    const int r0 = (lane >= F2PT) ? 1 : 0;
    const int j0 = lane - F2PT * r0;
    const float* sp0 = s_st + r0 * STRIDE_ST + 2 * j0;
    float* gp0 = out + (size_t)(b0 + r0) * OUTROW + 6 + 2 * j0;

#define STEP(th, vx, vy, om, x, y, C0, C1, C2, myst, S) do {                  \
    float s_, c_; __sincosf(th, &s_, &c_);                                    \
    float vxb = fmaf(vx, c_,  vy * s_);                                       \
    float vyb = fmaf(vy, c_, -vx * s_);                                       \
    float d0 = (C0) - vxb, d1 = (C1) - vyb, d2 = (C2) - om;                   \
    float F0 = fmaf(A00, d0, fmaf(-dv0, vxb, -dc0 * sgnf(vxb)));              \
    float F1 = fmaf(A11, d1, fmaf(A12, d2, fmaf(-dv1, vyb, -dc1 * sgnf(vyb))));\
    float F2 = fmaf(A12, d1, fmaf(A22, d2, fmaf(-dv2, om,  -dc2 * sgnf(om))));\
    float tau = F2 - (dxo * F1 - dyo * F0);                                   \
    float ax = F0 * invM, ay = F1 * invM, al = tau * invI;                    \
    float om2 = om * om;                                                      \
    float axb = fmaf(-al, dyo, fmaf(-om2, dxo, ax));                          \
    float ayb = fmaf( al, dxo, fmaf(-om2, dyo, ay));                          \
    float axw = fmaf(axb, c_, -ayb * s_);                                     \
    float ayw = fmaf(axb, s_,  ayb * c_);                                     \
    vx = fmaf(axw, DT, vx);                                                   \
    vy = fmaf(ayw, DT, vy);                                                   \
    om = fmaf(al,  DT, om);                                                   \
    x  = fmaf(vx, DT, x);                                                     \
    y  = fmaf(vy, DT, y);                                                     \
    th = fmaf(om, DT, th);                                                    \
    th = (th >  PI_F) ? th - TWOPI_F : th;                                    \
    th = (th < -PI_F) ? th + TWOPI_F : th;                                    \
    *(float2*)(myst + 6*(S) + 0) = make_float2(x, y);                         \
    *(float2*)(myst + 6*(S) + 2) = make_float2(th, vx);                       \
    *(float2*)(myst + 6*(S) + 4) = make_float2(vy, om);                       \
} while (0)

    for (int tile = 0; tile < NTILES; ++tile) {
        const int buf = tile & 1;

        // Prefetch next tile's commands into registers (overlaps compute)
        float4 pf[12];
        if (tile + 1 < NTILES) {
            const float* src = cmdbase + (tile + 1) * CPTF;
#pragma unroll
            for (int i = 0; i < 12; i++)
                pf[i] = *(const float4*)(src + pf_goff[i]);
        }

        // ── Compute K steps, 2 robots interleaved ──
        const float* cb = s_cmd[buf];
#pragma unroll
        for (int s = 0; s < K; s++) {
            float CA0 = cb[(3*s + 0) * RPB + lane];
            float CA1 = cb[(3*s + 1) * RPB + lane];
            float CA2 = cb[(3*s + 2) * RPB + lane];
            float CB0 = cb[(3*s + 0) * RPB + lane + 32];
            float CB1 = cb[(3*s + 1) * RPB + lane + 32];
            float CB2 = cb[(3*s + 2) * RPB + lane + 32];
            STEP(thA, vxA, vyA, omA, xA, yA, CA0, CA1, CA2, mystA, s);
            STEP(thB, vxB, vyB, omB, xB, yB, CB0, CB1, CB2, mystB, s);
        }
        __syncwarp();

        // ── Cooperative coalesced store of state tile (float2 units) ──
        {
            float*       gp = gp0 + tile * SPTF;
            const float* sp = sp0;
            int j = j0;
#pragma unroll 4
            for (int i = 0; i < 48; i++) {
                float2 v = *(const float2*)sp;
                *(float2*)gp = v;
                // advance by 32 float2 with wrap over rows of 24
                j += 8;                                  // one mandatory wrap
                gp += OUTROW + 16;
                sp += STRIDE_ST + 16;
                if (j >= F2PT) {                         // possible second wrap
                    j -= F2PT;
                    gp += OUTROW - 2 * F2PT;
                    sp += STRIDE_ST - 2 * F2PT;
                }
            }
        }

        // ── Fill other cmd buffer (transposed scatter) ──
        if (tile + 1 < NTILES) {
            float* dst = s_cmd[buf ^ 1];
#pragma unroll
            for (int i = 0; i < 12; i++) {
                dst[pf_soff[i] + 0 * RPB] = pf[i].x;
                dst[pf_soff[i] + 1 * RPB] = pf[i].y;
                dst[pf_soff[i] + 2 * RPB] = pf[i].z;
                dst[pf_soff[i] + 3 * RPB] = pf[i].w;
            }
        }
        __syncwarp();
    }
#undef STEP
}

extern "C" void kernel_launch(void* const* d_in, const int* in_sizes, int n_in,
                              void* d_out, int out_size)
{
    const float* init = (const float*)d_in[0];  // (8192, 6)
    const float* cmd  = (const float*)d_in[1];  // (8192, 1024, 3)
    const float* com  = (const float*)d_in[2];  // (2,)
    const float* pI   = (const float*)d_in[3];
    const float* pG   = (const float*)d_in[4];
    const float* pT   = (const float*)d_in[5];
    const float* pDv  = (const float*)d_in[6];  // (3,)
    const float* pDc  = (const float*)d_in[7];  // (3,)
    float* out = (float*)d_out;                 // (8192, 1025, 6)

    omni_sim_kernel<<<NB / RPB, 32>>>(init, cmd, com, pI, pG, pT, pDv, pDc, out);
}